// round 3
// baseline (speedup 1.0000x reference)
#include <cuda_runtime.h>
#include <cuda_bf16.h>
#include <math.h>

// Problem constants
#define BGRAPH 128
#define NNODE  512
#define NN     (BGRAPH*NNODE)      // 65536
#define DFEAT  128
#define EDGES  524288
#define KEEP1  410
#define KEEP2  328

// ---------------- scratch (device globals; no runtime allocation) ----------------
__device__ float g_agg[NN*DFEAT];   // aggregated neighbor features
__device__ float g_h  [NN*DFEAT];   // conv1 output (then gated in place)
__device__ float g_h2 [NN*DFEAT];   // conv2 output
__device__ int   g_deg[NN];
__device__ int   g_cursor[NN];
__device__ int   g_off[NN+1];
__device__ int   g_csr[EDGES];
__device__ unsigned char g_m1[NN];
__device__ float g_x1[BGRAPH*256];
__device__ float g_x2[BGRAPH*256];

// ---------------- packed fp32x2 helpers (Blackwell) ----------------
__device__ __forceinline__ unsigned long long pk2(float x) {
    unsigned long long d;
    asm("mov.b64 %0, {%1, %1};" : "=l"(d) : "f"(x));
    return d;
}
__device__ __forceinline__ unsigned long long ffma2(unsigned long long a,
                                                    unsigned long long b,
                                                    unsigned long long c) {
    unsigned long long d;
    asm("fma.rn.f32x2 %0, %1, %2, %3;" : "=l"(d) : "l"(a), "l"(b), "l"(c));
    return d;
}
__device__ __forceinline__ void unpk2(unsigned long long v, float& lo, float& hi) {
    asm("mov.b64 {%0, %1}, %2;" : "=f"(lo), "=f"(hi) : "l"(v));
}

// ---------------- CSR build ----------------
__global__ void zero_counts_kernel() {
    int i = blockIdx.x * blockDim.x + threadIdx.x;
    if (i < NN) { g_deg[i] = 0; g_cursor[i] = 0; }
}

__global__ void hist_kernel(const int* __restrict__ dst) {
    int i = blockIdx.x * blockDim.x + threadIdx.x;
    if (i < EDGES) atomicAdd(&g_deg[dst[i]], 1);
}

__global__ void scan_kernel() {
    __shared__ int sp[1024];
    int tid = threadIdx.x;
    int base = tid * 64;
    int s = 0;
#pragma unroll 8
    for (int i = 0; i < 64; ++i) s += g_deg[base + i];
    sp[tid] = s;
    __syncthreads();
    for (int off = 1; off < 1024; off <<= 1) {
        int v = (tid >= off) ? sp[tid - off] : 0;
        __syncthreads();
        sp[tid] += v;
        __syncthreads();
    }
    int run = sp[tid] - s;   // exclusive prefix
    for (int i = 0; i < 64; ++i) {
        g_off[base + i] = run;
        run += g_deg[base + i];
    }
    if (tid == 1023) g_off[NN] = run;
}

__global__ void scatter_kernel(const int* __restrict__ src, const int* __restrict__ dst) {
    int i = blockIdx.x * blockDim.x + threadIdx.x;
    if (i < EDGES) {
        int d = dst[i];
        int pos = atomicAdd(&g_cursor[d], 1);
        g_csr[g_off[d] + pos] = src[i];
    }
}

// ---------------- neighbor aggregation (gather-sum, warp per node) ----------------
template<int LAYER>
__global__ void agg_gather_kernel(const float* __restrict__ xin) {
    const float* feat = (LAYER == 1) ? xin : g_h;
    int gw = (blockIdx.x * blockDim.x + threadIdx.x) >> 5;
    int lane = threadIdx.x & 31;
    if (gw >= NN) return;
    int beg = g_off[gw];
    int end = g_off[gw + 1];
    float a0 = 0.f, a1 = 0.f, a2 = 0.f, a3 = 0.f;
    const float4* f4 = (const float4*)feat;
    for (int e = beg; e < end; ++e) {
        int s = __ldg(&g_csr[e]);
        float4 v = __ldg(f4 + (size_t)s * 32 + lane);
        a0 += v.x; a1 += v.y; a2 += v.z; a3 += v.w;
    }
    float4 o = make_float4(a0, a1, a2, a3);
    ((float4*)g_agg)[(size_t)gw * 32 + lane] = o;
}

// ---------------- fused conv GEMM: out = relu(A1@Wr + A2@Wn + b) ----------------
// Tile 128x128, K=256 (two 128 sources), 256 threads, f32x2 packed FMA (rows paired).
template<int LAYER>
__global__ void __launch_bounds__(256, 2)
conv_gemm_kernel(const float* __restrict__ A1in,
                 const float* __restrict__ Wr,
                 const float* __restrict__ Wn,
                 const float* __restrict__ bias) {
    const float* A1 = (LAYER == 1) ? A1in : g_h;
    const float* A2 = g_agg;
    float* Out = (LAYER == 1) ? g_h : g_h2;

    __shared__ float As[8][128];
    __shared__ float Ws[8][128];

    int tid = threadIdx.x;
    int cx = tid & 31;        // column group: cols cx + 32*j
    int ry = tid >> 5;        // row group: rows ry*16 .. ry*16+15 (8 pairs)
    int row0 = blockIdx.x * 128;
    int lrow = tid >> 1;              // A loader row 0..127
    int lk4 = (tid & 1) * 4;          // A loader k sub-offset

    unsigned long long acc[8][4];
#pragma unroll
    for (int r = 0; r < 8; ++r)
#pragma unroll
        for (int j = 0; j < 4; ++j) acc[r][j] = 0ull;

#pragma unroll 1
    for (int chunk = 0; chunk < 32; ++chunk) {
        const float* A = (chunk < 16) ? A1 : A2;
        const float* W = (chunk < 16) ? Wr : Wn;
        int k0 = (chunk & 15) * 8;

        float4 av = *(const float4*)&A[(size_t)(row0 + lrow) * 128 + k0 + lk4];
        float4 wv = *(const float4*)&W[(size_t)(k0 + ry) * 128 + cx * 4];

        __syncthreads();   // previous iteration's reads done
        As[lk4 + 0][lrow] = av.x;
        As[lk4 + 1][lrow] = av.y;
        As[lk4 + 2][lrow] = av.z;
        As[lk4 + 3][lrow] = av.w;
        *(float4*)&Ws[ry][cx * 4] = wv;
        __syncthreads();

#pragma unroll
        for (int k = 0; k < 8; ++k) {
            unsigned long long ap[8];
#pragma unroll
            for (int r = 0; r < 8; ++r)
                ap[r] = *(const unsigned long long*)&As[k][ry * 16 + 2 * r];
#pragma unroll
            for (int j = 0; j < 4; ++j) {
                unsigned long long wp = pk2(Ws[k][cx + 32 * j]);
#pragma unroll
                for (int r = 0; r < 8; ++r)
                    acc[r][j] = ffma2(ap[r], wp, acc[r][j]);
            }
        }
    }

#pragma unroll
    for (int j = 0; j < 4; ++j) {
        int col = cx + 32 * j;
        float bb = __ldg(&bias[col]);
#pragma unroll
        for (int r = 0; r < 8; ++r) {
            float lo, hi;
            unpk2(acc[r][j], lo, hi);
            int row = row0 + ry * 16 + 2 * r;
            Out[(size_t)row * 128 + col]       = fmaxf(lo + bb, 0.f);
            Out[(size_t)(row + 1) * 128 + col] = fmaxf(hi + bb, 0.f);
        }
    }
}

// ---------------- pool: score + topk + gate + readout (one block per graph) ----------------
template<int LAYER>
__global__ void __launch_bounds__(512)
pool_kernel(const float* __restrict__ p) {
    constexpr int KK = (LAYER == 1) ? KEEP1 : KEEP2;
    float* h = (LAYER == 1) ? g_h : g_h2;
    float* xout = (LAYER == 1) ? g_x1 : g_x2;

    int b = blockIdx.x;
    int tid = threadIdx.x;
    int lane = tid & 31, w = tid >> 5;   // 16 warps

    __shared__ float sval[512];
    __shared__ float ssort[512];
    __shared__ float sgate[512];
    __shared__ int   ssel[512];
    __shared__ int   sscan[512];
    __shared__ float rmax[16 * 128];
    __shared__ float rsum[16 * 128];

    float p0 = p[lane], p1v = p[lane + 32], p2v = p[lane + 64], p3v = p[lane + 96];
    float n2 = p0 * p0 + p1v * p1v + p2v * p2v + p3v * p3v;
#pragma unroll
    for (int o = 16; o; o >>= 1) n2 += __shfl_xor_sync(0xffffffffu, n2, o);
    float inv = rsqrtf(n2);

    float* hb = h + (size_t)b * NNODE * 128;

    // scores: warp per node
    for (int n = w; n < NNODE; n += 16) {
        const float* r = hb + n * 128;
        float acc = r[lane] * p0 + r[lane + 32] * p1v + r[lane + 64] * p2v + r[lane + 96] * p3v;
#pragma unroll
        for (int o = 16; o; o >>= 1) acc += __shfl_xor_sync(0xffffffffu, acc, o);
        if (lane == 0) {
            float s = acc * inv;
            if (LAYER == 2 && !g_m1[b * NNODE + n]) s = -INFINITY;
            sval[n] = s;
        }
    }
    __syncthreads();

    // bitonic sort (descending) to find threshold = K-th largest
    ssort[tid] = sval[tid];
    __syncthreads();
    for (int k2 = 2; k2 <= 512; k2 <<= 1) {
        for (int j = k2 >> 1; j > 0; j >>= 1) {
            int ixj = tid ^ j;
            float a = ssort[tid];
            float bv = ssort[ixj];
            bool desc = ((tid & k2) == 0);
            bool isLower = (tid < ixj);
            float res = (desc == isLower) ? fmaxf(a, bv) : fminf(a, bv);
            __syncthreads();
            ssort[tid] = res;
            __syncthreads();
        }
    }
    float t = ssort[KK - 1];

    // exact selection with lowest-index tie-break (matches lax.top_k)
    float s = sval[tid];
    int fgt = (s > t) ? 1 : 0;
    int feq = (s == t) ? 1 : 0;
    sscan[tid] = (fgt << 16) | feq;
    __syncthreads();
    for (int off = 1; off < 512; off <<= 1) {
        int v = (tid >= off) ? sscan[tid - off] : 0;
        __syncthreads();
        sscan[tid] += v;
        __syncthreads();
    }
    int totgt = sscan[511] >> 16;
    int preeq = (sscan[tid] & 0xffff) - feq;
    int sel = fgt | (feq && (preeq < KK - totgt));
    ssel[tid] = sel;
    sgate[tid] = sel ? tanhf(s) : 0.f;
    if (LAYER == 1) g_m1[b * NNODE + tid] = (unsigned char)sel;
    __syncthreads();

    // gate (+writeback for layer1) + readout (max & mean over kept nodes)
    float mx0 = -INFINITY, mx1 = -INFINITY, mx2 = -INFINITY, mx3 = -INFINITY;
    float sm0 = 0.f, sm1 = 0.f, sm2 = 0.f, sm3 = 0.f;
    for (int n = w; n < NNODE; n += 16) {
        float g = sgate[n];
        int se = ssel[n];
        float* r = hb + n * 128;
        float v0 = r[lane] * g;
        float v1 = r[lane + 32] * g;
        float v2 = r[lane + 64] * g;
        float v3 = r[lane + 96] * g;
        if (LAYER == 1) {
            r[lane] = v0; r[lane + 32] = v1; r[lane + 64] = v2; r[lane + 96] = v3;
        }
        if (se) {
            mx0 = fmaxf(mx0, v0); mx1 = fmaxf(mx1, v1);
            mx2 = fmaxf(mx2, v2); mx3 = fmaxf(mx3, v3);
        }
        sm0 += v0; sm1 += v1; sm2 += v2; sm3 += v3;
    }
    rmax[w * 128 + lane]      = mx0;
    rmax[w * 128 + lane + 32] = mx1;
    rmax[w * 128 + lane + 64] = mx2;
    rmax[w * 128 + lane + 96] = mx3;
    rsum[w * 128 + lane]      = sm0;
    rsum[w * 128 + lane + 32] = sm1;
    rsum[w * 128 + lane + 64] = sm2;
    rsum[w * 128 + lane + 96] = sm3;
    __syncthreads();
    if (tid < 128) {
        float M = -INFINITY, S = 0.f;
#pragma unroll
        for (int i = 0; i < 16; ++i) {
            M = fmaxf(M, rmax[i * 128 + tid]);
            S += rsum[i * 128 + tid];
        }
        xout[b * 256 + tid] = M;
        xout[b * 256 + 128 + tid] = S / (float)KK;
    }
}

// ---------------- MLP head ----------------
__global__ void __launch_bounds__(128)
head_kernel(const float* __restrict__ lw1, const float* __restrict__ lb1,
            const float* __restrict__ lw2, const float* __restrict__ lb2,
            const float* __restrict__ lw3, const float* __restrict__ lb3,
            float* __restrict__ out) {
    int b = blockIdx.x;
    int tid = threadIdx.x;   // 128
    __shared__ float z[256], z1[128], z2[64];
    z[tid]       = g_x1[b * 256 + tid]       + g_x2[b * 256 + tid];
    z[tid + 128] = g_x1[b * 256 + 128 + tid] + g_x2[b * 256 + 128 + tid];
    __syncthreads();
    float a = lb1[tid];
#pragma unroll 8
    for (int i = 0; i < 256; ++i) a += z[i] * lw1[i * 128 + tid];
    z1[tid] = fmaxf(a, 0.f);
    __syncthreads();
    if (tid < 64) {
        float a2 = lb2[tid];
#pragma unroll 8
        for (int i = 0; i < 128; ++i) a2 += z1[i] * lw2[i * 64 + tid];
        z2[tid] = fmaxf(a2, 0.f);
    }
    __syncthreads();
    if (tid == 0) {
        float a3 = lb3[0];
#pragma unroll 8
        for (int i = 0; i < 64; ++i) a3 += z2[i] * lw3[i];
        out[b] = 1.f / (1.f + expf(-a3));
    }
}

// ---------------- launch ----------------
extern "C" void kernel_launch(void* const* d_in, const int* in_sizes, int n_in,
                              void* d_out, int out_size) {
    const float* x   = (const float*)d_in[0];
    const int*   ei  = (const int*)d_in[1];
    const float* W1r = (const float*)d_in[2];
    const float* W1n = (const float*)d_in[3];
    const float* b1  = (const float*)d_in[4];
    const float* p1  = (const float*)d_in[5];
    const float* W2r = (const float*)d_in[6];
    const float* W2n = (const float*)d_in[7];
    const float* b2  = (const float*)d_in[8];
    const float* p2  = (const float*)d_in[9];
    const float* lw1 = (const float*)d_in[10];
    const float* lb1 = (const float*)d_in[11];
    const float* lw2 = (const float*)d_in[12];
    const float* lb2 = (const float*)d_in[13];
    const float* lw3 = (const float*)d_in[14];
    const float* lb3 = (const float*)d_in[15];
    float* out = (float*)d_out;

    const int* src = ei;
    const int* dst = ei + EDGES;

    // CSR build (edges are an input, rebuilt every call — stateless)
    zero_counts_kernel<<<NN / 256, 256>>>();
    hist_kernel<<<EDGES / 256, 256>>>(dst);
    scan_kernel<<<1, 1024>>>();
    scatter_kernel<<<EDGES / 256, 256>>>(src, dst);

    // conv1
    agg_gather_kernel<1><<<NN * 32 / 256, 256>>>(x);
    conv_gemm_kernel<1><<<NN / 128, 256>>>(x, W1r, W1n, b1);
    pool_kernel<1><<<BGRAPH, 512>>>(p1);

    // conv2 (on gated h)
    agg_gather_kernel<2><<<NN * 32 / 256, 256>>>(nullptr);
    conv_gemm_kernel<2><<<NN / 128, 256>>>(nullptr, W2r, W2n, b2);
    pool_kernel<2><<<BGRAPH, 512>>>(p2);

    // head
    head_kernel<<<BGRAPH, 128>>>(lw1, lb1, lw2, lb2, lw3, lb3, out);
}